// round 7
// baseline (speedup 1.0000x reference)
#include <cuda_runtime.h>
#include <cstdint>

#define NPTS     16384
#define NB       256
#define XMIN     (-4.0f)
#define BW       0.03125f          // 8/256, exact in binary
#define INVBW    32.0f
#define STHREADS 1024
#define MTHREADS 64
#define MBLOCKS  512               // 256 per direction
#define FTHREADS 512

#define POS_INF __int_as_float(0x7f800000)

// ---------------- persistent scratch (no allocations; rewritten every call) --
__device__ float4 g_sorted[2][NPTS];        // (x, y, z, |p|^2), bucket-sorted by x
__device__ int    g_boff[2][NB + 1];        // bucket start offsets
__device__ float  g_partial[MBLOCKS];       // per-block distance sums

__device__ __forceinline__ int bucket_of(float x) {
    int b = (int)floorf((x - XMIN) * INVBW);
    return min(max(b, 0), NB - 1);
}

// ---------------- kernel 1: counting sort by x-bucket (one block per set) ----
__global__ void __launch_bounds__(STHREADS)
sort_kernel(const float* __restrict__ pred, const float* __restrict__ targ) {
    __shared__ int cnt[NB];
    __shared__ int cur[NB];
    const int set = blockIdx.x;                 // 0 = pred, 1 = targ
    const float* __restrict__ src = set ? targ : pred;
    const int tid = threadIdx.x;

    for (int b = tid; b < NB; b += STHREADS) cnt[b] = 0;
    __syncthreads();

    for (int i = tid; i < NPTS; i += STHREADS)
        atomicAdd(&cnt[bucket_of(src[3 * i])], 1);
    __syncthreads();

    if (tid == 0) {
        int acc = 0;
        for (int b = 0; b < NB; b++) {
            g_boff[set][b] = acc;
            cur[b] = acc;
            acc += cnt[b];
        }
        g_boff[set][NB] = acc;
    }
    __syncthreads();

    for (int i = tid; i < NPTS; i += STHREADS) {
        float x = src[3 * i + 0];
        float y = src[3 * i + 1];
        float z = src[3 * i + 2];
        int pos = atomicAdd(&cur[bucket_of(x)], 1);
        g_sorted[set][pos] = make_float4(x, y, z, x * x + y * y + z * z);
    }
}

// ---------------- kernel 2: windowed nearest-neighbor search ----------------
// One query per lane; warp lanes are CONSECUTIVE sorted queries, so the warp
// shares a narrow x-window. Warp scans its home bucket span, then expands
// left/right; each lane prunes when the bucket-edge bound exceeds its best d^2.
// Unpruned lanes force the warp to keep scanning; extra candidates for pruned
// lanes only ever tighten a min, so no masking is needed for correctness.
__global__ void __launch_bounds__(MTHREADS)
main_kernel() {
    const int bid = blockIdx.x;
    const int dir = bid >> 8;                  // 256 blocks per direction
    const int aset = dir, bset = 1 - dir;
    const int ai = (bid & 255) * MTHREADS + threadIdx.x;

    const float4 a = g_sorted[aset][ai];
    const float amx = -2.0f * a.x;
    const float amy = -2.0f * a.y;
    const float amz = -2.0f * a.z;
    const float ca  = a.w;

    const float4* __restrict__ B = g_sorted[bset];
    const int*    __restrict__ boff = g_boff[bset];

    float best = POS_INF;                      // min over s = cb - 2 a.b

    const int qa  = bucket_of(a.x);
    const int qlo = __reduce_min_sync(0xFFFFFFFFu, (unsigned)qa);
    const int qhi = __reduce_max_sync(0xFFFFFFFFu, (unsigned)qa);

    // home span
    for (int b = qlo; b <= qhi; b++) {
        const int e = boff[b + 1];
        for (int i = boff[b]; i < e; i++) {
            float4 bv = B[i];                  // same address across lanes
            float s = fmaf(amx, bv.x, fmaf(amy, bv.y, fmaf(amz, bv.z, bv.w)));
            best = fminf(best, s);
        }
    }

    // ring expansion
    int L = qlo - 1, R = qhi + 1;
    for (;;) {
        const float bound = ca + best;         // current best d^2 (INF at start)
        bool needL = false, needR = false;
        if (L >= 0) {
            float lb = a.x - (XMIN + (float)(L + 1) * BW);   // >= 0 for L < qa
            needL = (lb * lb < bound);
        }
        if (R < NB) {
            float lb = (XMIN + (float)R * BW) - a.x;         // >= 0 for R > qa
            needR = (lb * lb < bound);
        }
        const unsigned mL = __ballot_sync(0xFFFFFFFFu, needL);
        const unsigned mR = __ballot_sync(0xFFFFFFFFu, needR);
        if (!(mL | mR)) break;
        if (mL) {
            const int e = boff[L + 1];
            for (int i = boff[L]; i < e; i++) {
                float4 bv = B[i];
                float s = fmaf(amx, bv.x, fmaf(amy, bv.y, fmaf(amz, bv.z, bv.w)));
                best = fminf(best, s);
            }
            L--;
        }
        if (mR) {
            const int e = boff[R + 1];
            for (int i = boff[R]; i < e; i++) {
                float4 bv = B[i];
                float s = fmaf(amx, bv.x, fmaf(amy, bv.y, fmaf(amz, bv.z, bv.w)));
                best = fminf(best, s);
            }
            R++;
        }
    }

    float d = sqrtf(fmaxf(ca + best, 0.0f));

    // block reduction (2 warps)
    __shared__ float sRed[MTHREADS / 32];
#pragma unroll
    for (int s = 16; s > 0; s >>= 1)
        d += __shfl_xor_sync(0xFFFFFFFFu, d, s);
    if ((threadIdx.x & 31) == 0) sRed[threadIdx.x >> 5] = d;
    __syncthreads();
    if (threadIdx.x == 0) g_partial[bid] = sRed[0] + sRed[1];
}

// ---------------- kernel 3: final sum ----------------
__global__ void __launch_bounds__(FTHREADS)
final_kernel(float* __restrict__ out) {
    float v = g_partial[threadIdx.x];
#pragma unroll
    for (int s = 16; s > 0; s >>= 1)
        v += __shfl_xor_sync(0xFFFFFFFFu, v, s);
    __shared__ float sRed[FTHREADS / 32];
    if ((threadIdx.x & 31) == 0) sRed[threadIdx.x >> 5] = v;
    __syncthreads();
    if (threadIdx.x == 0) {
        float t = 0.0f;
#pragma unroll
        for (int w = 0; w < FTHREADS / 32; w++) t += sRed[w];
        out[0] = t * (1.0f / (float)NPTS);
    }
}

// ---------------- launch ----------------
extern "C" void kernel_launch(void* const* d_in, const int* in_sizes, int n_in,
                              void* d_out, int out_size) {
    const float* pred = (const float*)d_in[0];
    const float* targ = (const float*)d_in[1];
    float* out = (float*)d_out;

    sort_kernel<<<2, STHREADS>>>(pred, targ);
    main_kernel<<<MBLOCKS, MTHREADS>>>();
    final_kernel<<<1, FTHREADS>>>(out);
}

// round 8
// speedup vs baseline: 3.6124x; 3.6124x over previous
#include <cuda_runtime.h>
#include <cstdint>

#define NPTS     16384
#define NB       256
#define XMIN     (-4.0f)
#define BW       0.03125f           // 8/256, exact in binary
#define INVBW    32.0f
#define HBLOCKS  64                 // hist/scatter blocks (32 per set)
#define HTHREADS 256
#define PPB      512                // points per hist/scatter block
#define MTHREADS 64
#define MBLOCKS  512                // 256 per direction, 64 queries each
#define TILE     256
#define FTHREADS 512

#define POS_INF __int_as_float(0x7f800000)

// ---------------- persistent scratch (rewritten every call) ----------------
__device__ int    g_part[HBLOCKS][NB];     // per-block partial histograms
__device__ int    g_boff[2][NB + 1];       // bucket start offsets
__device__ int    g_cur[2][NB];            // scatter cursors
__device__ float4 g_sorted[2][NPTS];       // (x,y,z,|p|^2), bucket-sorted by x
__device__ float  g_partial[MBLOCKS];      // per-block distance sums

__device__ __forceinline__ int bucket_of(float x) {
    int b = (int)floorf((x - XMIN) * INVBW);
    return min(max(b, 0), NB - 1);
}
// unseen-left points (bucket <= b) have x < rightEdge(b); clamped tail in b=255
__device__ __forceinline__ float right_edge(int b) {
    return (b >= NB - 1) ? 1e30f : (XMIN + (float)(b + 1) * BW);
}
// unseen-right points (bucket >= b) have x >= leftEdge(b); clamped tail in b=0
__device__ __forceinline__ float left_edge(int b) {
    return (b <= 0) ? -1e30f : (XMIN + (float)b * BW);
}

// ---------------- packed f32x2 helpers ----------------
__device__ __forceinline__ unsigned long long pack2(float lo, float hi) {
    unsigned long long r;
    asm("mov.b64 %0, {%1, %2};" : "=l"(r) : "f"(lo), "f"(hi));
    return r;
}
__device__ __forceinline__ unsigned long long fma2(unsigned long long a,
                                                   unsigned long long b,
                                                   unsigned long long c) {
    unsigned long long d;
    asm("fma.rn.f32x2 %0, %1, %2, %3;" : "=l"(d) : "l"(a), "l"(b), "l"(c));
    return d;
}
__device__ __forceinline__ void unpack2(unsigned long long v, float& lo, float& hi) {
    asm("mov.b64 {%0, %1}, %2;" : "=f"(lo), "=f"(hi) : "l"(v));
}

// ---------------- kernel 1: partial histograms (64 blocks) ----------------
__global__ void __launch_bounds__(HTHREADS)
hist_kernel(const float* __restrict__ pred, const float* __restrict__ targ) {
    __shared__ int h[NB];
    const int set   = blockIdx.x >> 5;
    const int slice = blockIdx.x & 31;
    const float* __restrict__ src = set ? targ : pred;
    const int tid = threadIdx.x;

    h[tid] = 0;
    __syncthreads();
#pragma unroll
    for (int r = 0; r < PPB / HTHREADS; r++) {
        const int i = slice * PPB + r * HTHREADS + tid;
        atomicAdd(&h[bucket_of(src[3 * i])], 1);
    }
    __syncthreads();
    g_part[blockIdx.x][tid] = h[tid];
}

// ---------------- kernel 2: sum partials + prefix scan (1 block) ----------
__global__ void __launch_bounds__(2 * NB)
scan_kernel() {
    __shared__ int sVal[2 * NB];
    const int tid = threadIdx.x;
    const int set = tid >> 8;
    const int b   = tid & (NB - 1);

    int cnt = 0;
#pragma unroll 8
    for (int k = 0; k < 32; k++) cnt += g_part[set * 32 + k][b];

    sVal[tid] = cnt;
    __syncthreads();
    // Hillis-Steele inclusive scan within each 256-entry segment
    for (int st = 1; st < NB; st <<= 1) {
        int add = (b >= st) ? sVal[tid - st] : 0;
        __syncthreads();
        sVal[tid] += add;
        __syncthreads();
    }
    const int excl = sVal[tid] - cnt;
    g_boff[set][b] = excl;
    g_cur[set][b]  = excl;
    if (b == NB - 1) g_boff[set][NB] = sVal[tid];
}

// ---------------- kernel 3: scatter into bucket-sorted order --------------
__global__ void __launch_bounds__(HTHREADS)
scatter_kernel(const float* __restrict__ pred, const float* __restrict__ targ) {
    const int set   = blockIdx.x >> 5;
    const int slice = blockIdx.x & 31;
    const float* __restrict__ src = set ? targ : pred;
    const int tid = threadIdx.x;

#pragma unroll
    for (int r = 0; r < PPB / HTHREADS; r++) {
        const int i = slice * PPB + r * HTHREADS + tid;
        float x = src[3 * i + 0];
        float y = src[3 * i + 1];
        float z = src[3 * i + 2];
        int pos = atomicAdd(&g_cur[set][bucket_of(x)], 1);
        g_sorted[set][pos] = make_float4(x, y, z, x * x + y * y + z * z);
    }
}

// ---------------- kernel 4: windowed NN via staged tiles ------------------
// Block = 64 consecutive sorted queries of one direction. Home tile of 256
// B points at the matching rank is staged into smem and scanned with packed
// f32x2 math; then 256-point tiles expand left/right while any lane's
// bucket-edge bound says the true NN could still be outside the window.
__global__ void __launch_bounds__(MTHREADS)
main_kernel() {
    __shared__ __align__(16) float sx[TILE], sy[TILE], sz[TILE], sc[TILE];

    const int bid  = blockIdx.x;
    const int dir  = bid >> 8;
    const int aset = dir, bset = 1 - dir;
    const int q0   = (bid & 255) * MTHREADS;
    const int tid  = threadIdx.x;
    const int q    = q0 + tid;

    const float4 a = g_sorted[aset][q];
    const unsigned long long ax2 = pack2(-2.0f * a.x, -2.0f * a.x);
    const unsigned long long ay2 = pack2(-2.0f * a.y, -2.0f * a.y);
    const unsigned long long az2 = pack2(-2.0f * a.z, -2.0f * a.z);
    const float ca = a.w;

    const float4* __restrict__ B = g_sorted[bset];

    // stage tile [t0, t0+256) into smem (always a full in-range tile)
    auto stage = [&](int t0) {
#pragma unroll
        for (int r = 0; r < 4; r++) {
            const int s = tid * 4 + r;
            float4 v = B[t0 + s];
            sx[s] = v.x; sy[s] = v.y; sz[s] = v.z; sc[s] = v.w;
        }
    };

    float mlo = POS_INF, mhi = POS_INF;
    auto scan = [&]() {
#pragma unroll 8
        for (int j = 0; j < TILE; j += 4) {
            ulonglong2 vx = *(const ulonglong2*)&sx[j];
            ulonglong2 vy = *(const ulonglong2*)&sy[j];
            ulonglong2 vz = *(const ulonglong2*)&sz[j];
            ulonglong2 vc = *(const ulonglong2*)&sc[j];
            unsigned long long s01 = fma2(ax2, vx.x, fma2(ay2, vy.x, fma2(az2, vz.x, vc.x)));
            unsigned long long s23 = fma2(ax2, vx.y, fma2(ay2, vy.y, fma2(az2, vz.y, vc.y)));
            float s0, s1, s2, s3;
            unpack2(s01, s0, s1);
            unpack2(s23, s2, s3);
            mlo = fminf(mlo, fminf(s0, s2));
            mhi = fminf(mhi, fminf(s1, s3));
        }
    };

    // home tile centered at the matching rank
    int lo = q0 + MTHREADS / 2 - TILE / 2;
    lo = min(max(lo, 0), NPTS - TILE);
    int hi = lo + TILE;

    stage(lo);
    __syncthreads();
    float eL = right_edge(bucket_of(sx[0]));          // bound for unseen-left
    float eR = left_edge(bucket_of(sx[TILE - 1]));    // bound for unseen-right
    scan();

    for (;;) {
        const float best  = fminf(mlo, mhi);
        const float bound = fmaxf(ca + best, 0.0f);   // current best d^2
        const float dxl = fmaxf(a.x - eL, 0.0f);
        const float dxr = fmaxf(eR - a.x, 0.0f);
        const int needL = (lo > 0)    && (dxl * dxl < bound);
        const int needR = (hi < NPTS) && (dxr * dxr < bound);
        const int vL = __syncthreads_or(needL);
        const int vR = __syncthreads_or(needR);
        if (!vL && !vR) break;

        if (vL) {
            const int nlo = max(lo - TILE, 0);        // full tile; overlap is harmless
            __syncthreads();                          // everyone done with smem
            stage(nlo);
            __syncthreads();
            eL = right_edge(bucket_of(sx[0]));
            scan();
            lo = nlo;
        }
        if (vR) {
            const int nhi = min(hi + TILE, NPTS);
            __syncthreads();
            stage(nhi - TILE);
            __syncthreads();
            eR = left_edge(bucket_of(sx[TILE - 1]));
            scan();
            hi = nhi;
        }
    }

    float d = sqrtf(fmaxf(ca + fminf(mlo, mhi), 0.0f));

    // block reduction (2 warps)
    __shared__ float sRed[MTHREADS / 32];
#pragma unroll
    for (int s = 16; s > 0; s >>= 1)
        d += __shfl_xor_sync(0xFFFFFFFFu, d, s);
    if ((tid & 31) == 0) sRed[tid >> 5] = d;
    __syncthreads();
    if (tid == 0) g_partial[bid] = sRed[0] + sRed[1];
}

// ---------------- kernel 5: final sum ----------------
__global__ void __launch_bounds__(FTHREADS)
final_kernel(float* __restrict__ out) {
    float v = g_partial[threadIdx.x];
#pragma unroll
    for (int s = 16; s > 0; s >>= 1)
        v += __shfl_xor_sync(0xFFFFFFFFu, v, s);
    __shared__ float sRed[FTHREADS / 32];
    if ((threadIdx.x & 31) == 0) sRed[threadIdx.x >> 5] = v;
    __syncthreads();
    if (threadIdx.x == 0) {
        float t = 0.0f;
#pragma unroll
        for (int w = 0; w < FTHREADS / 32; w++) t += sRed[w];
        out[0] = t * (1.0f / (float)NPTS);
    }
}

// ---------------- launch ----------------
extern "C" void kernel_launch(void* const* d_in, const int* in_sizes, int n_in,
                              void* d_out, int out_size) {
    const float* pred = (const float*)d_in[0];
    const float* targ = (const float*)d_in[1];
    float* out = (float*)d_out;

    hist_kernel<<<HBLOCKS, HTHREADS>>>(pred, targ);
    scan_kernel<<<1, 2 * NB>>>();
    scatter_kernel<<<HBLOCKS, HTHREADS>>>(pred, targ);
    main_kernel<<<MBLOCKS, MTHREADS>>>();
    final_kernel<<<1, FTHREADS>>>(out);
}